// round 1
// baseline (speedup 1.0000x reference)
#include <cuda_runtime.h>
#include <cstdint>

#define FULLMASK 0xFFFFFFFFu

// -------- packed weight storage (written by prep kernel each launch) --------
__device__ uint16_t           g_lut1[512];  // conv1: 9-bit neighborhood -> 16 channel sign bits
__device__ unsigned long long g_w2[48];     // conv2: [o][kernel_row] 48-bit packed (3 cols x 16 ch)
__device__ uint32_t           g_fcb[720];   // fc:    [k][72 words] sign bits over 2304 inputs

// ---------------------------------------------------------------------------
// Prep kernel: binarize + bit-pack all weights. 1 block, 768 threads.
// ---------------------------------------------------------------------------
__global__ void bnn_prep_kernel(const float* __restrict__ w1,
                                const float* __restrict__ w2,
                                const float* __restrict__ fcw) {
    __shared__ uint32_t w1p[16];
    int t = threadIdx.x;
    if (t < 16) {
        uint32_t b = 0;
        #pragma unroll
        for (int rc = 0; rc < 9; rc++)
            if (w1[t * 9 + rc] > 0.f) b |= (1u << rc);
        w1p[t] = b;
    }
    __syncthreads();
    if (t < 512) {
        uint32_t mask = 0;
        #pragma unroll
        for (int o = 0; o < 16; o++) {
            int m = __popc((uint32_t)t ^ w1p[o]);   // mismatches of 9; sum = 9-2m (never 0)
            if (m <= 4) mask |= (1u << o);
        }
        g_lut1[t] = (uint16_t)mask;
    }
    if (t < 48) {
        int o = t / 3, r = t % 3;
        unsigned long long v = 0;
        for (int i = 0; i < 16; i++)
            #pragma unroll
            for (int c = 0; c < 3; c++)
                if (w2[((o * 16 + i) * 3 + r) * 3 + c] > 0.f)
                    v |= (1ull << (c * 16 + i));
        g_w2[t] = v;
    }
    if (t < 720) {
        int k = t / 72, wd = t % 72;
        uint32_t v = 0;
        #pragma unroll
        for (int l = 0; l < 32; l++)
            if (fcw[k * 2304 + wd * 32 + l] > 0.f) v |= (1u << l);
        g_fcb[t] = v;
    }
}

// ---------------------------------------------------------------------------
// Main kernel: one image per CTA, 288 threads (9 warps).
// ---------------------------------------------------------------------------
__global__ __launch_bounds__(288, 4) void bnn_kernel(const float* __restrict__ x,
                                                     float* __restrict__ out) {
    __shared__ uint32_t           xb[28];        // thresholded input rows (bit j = col j)
    __shared__ uint16_t           s1m[676];      // conv1 sign masks, 26x26, bit c = channel c
    __shared__ int8_t             s3s[2304];     // ternary pooled activations [o*144 + p]
    __shared__ uint16_t           lut[512];
    __shared__ unsigned long long w2p[48];
    __shared__ uint32_t           fcb[720];
    __shared__ uint32_t           Pw[72], Mw[72];
    __shared__ int                lg[10];

    const int tid  = threadIdx.x;
    const int warp = tid >> 5;
    const int lane = tid & 31;
    const int b    = blockIdx.x;
    const float* xi = x + (size_t)b * 784;

    // weights -> smem
    if (tid < 256) ((uint32_t*)lut)[tid] = ((const uint32_t*)g_lut1)[tid];
    if (tid < 48)  w2p[tid] = g_w2[tid];
    for (int q = tid; q < 720; q += 288) fcb[q] = g_fcb[q];

    // ---- threshold + bit-pack input (x >= 0.2 -> +1) ----
    for (int row = warp; row < 28; row += 9) {
        int act = (lane < 28);
        float v = act ? xi[row * 28 + lane] : -1.f;
        uint32_t m = __ballot_sync(FULLMASK, act && (v >= 0.2f));
        if (lane == 0) xb[row] = m;
    }
    __syncthreads();

    // ---- conv1 + sign via LUT: 676 output pixels, 16 channels each ----
    for (int p = tid; p < 676; p += 288) {
        int i = p / 26, j = p - i * 26;
        uint32_t b9 = ((xb[i]     >> j) & 7u)
                    | (((xb[i + 1] >> j) & 7u) << 3)
                    | (((xb[i + 2] >> j) & 7u) << 6);
        s1m[p] = lut[b9];
    }
    __syncthreads();

    // ---- conv2 + sign + 2x2 avgpool + sign ----
    // thread = (pooled 2x2 spatial block, half of the 16 output channels)
    {
        int blk = tid >> 1;            // 0..143 pooled pixel
        int og  = (tid & 1) * 8;       // channel group
        int pi = blk / 12, pj = blk - pi * 12;
        int y0 = pi * 2, x0 = pj * 2;
        unsigned long long P[4][2];
        #pragma unroll
        for (int rr = 0; rr < 4; rr++) {
            const uint16_t* rowp = &s1m[(y0 + rr) * 26 + x0];
            unsigned long long m0 = rowp[0], m1 = rowp[1], m2 = rowp[2], m3 = rowp[3];
            P[rr][0] = m0 | (m1 << 16) | (m2 << 32);
            P[rr][1] = m1 | (m2 << 16) | (m3 << 32);
        }
        #pragma unroll
        for (int oo = 0; oo < 8; oo++) {
            int o = og + oo;
            unsigned long long wr0 = w2p[o * 3 + 0];
            unsigned long long wr1 = w2p[o * 3 + 1];
            unsigned long long wr2 = w2p[o * 3 + 2];
            int t4 = 0;
            #pragma unroll
            for (int dy = 0; dy < 2; dy++) {
                #pragma unroll
                for (int dx = 0; dx < 2; dx++) {
                    // mismatches over 144 bits; conv2 sum = 144 - 2m; sign: m<72 -> +1, ==72 -> 0
                    int m = __popcll(P[dy    ][dx] ^ wr0)
                          + __popcll(P[dy + 1][dx] ^ wr1)
                          + __popcll(P[dy + 2][dx] ^ wr2);
                    t4 += (m < 72) - (m > 72);
                }
            }
            s3s[o * 144 + blk] = (int8_t)((t4 > 0) - (t4 < 0));
        }
    }
    __syncthreads();

    // ---- pack ternary s3 into plus/minus bitmasks (72 words of 2304 bits) ----
    #pragma unroll
    for (int it = 0; it < 8; it++) {
        int v = s3s[it * 288 + tid];
        uint32_t Pm = __ballot_sync(FULLMASK, v > 0);
        uint32_t Mm = __ballot_sync(FULLMASK, v < 0);
        if (lane == 0) { Pw[it * 9 + warp] = Pm; Mw[it * 9 + warp] = Mm; }
    }
    __syncthreads();

    // ---- FC via AND+popcount: warp w -> logit k=w; warp 0 also k=9 ----
    for (int rep = 0; rep < 2; rep++) {
        if (rep == 1 && warp != 0) break;
        int k = (rep == 0) ? warp : 9;
        int acc = 0, c = 0;
        for (int wd = lane; wd < 72; wd += 32) {
            uint32_t p = Pw[wd], m = Mw[wd], wk = fcb[k * 72 + wd];
            acc += __popc(p & wk) - __popc(m & wk);
            c   += __popc(m) - __popc(p);
        }
        #pragma unroll
        for (int off = 16; off; off >>= 1) {
            acc += __shfl_xor_sync(FULLMASK, acc, off);
            c   += __shfl_xor_sync(FULLMASK, c, off);
        }
        if (lane == 0) lg[k] = 2 * acc + c;
    }
    __syncthreads();

    // ---- log_softmax over 10 logits (warp 0) ----
    if (warp == 0) {
        float v = (lane < 10) ? (float)lg[lane] : -3.0e38f;
        float mx = v;
        #pragma unroll
        for (int off = 16; off; off >>= 1) mx = fmaxf(mx, __shfl_xor_sync(FULLMASK, mx, off));
        float e = (lane < 10) ? expf(v - mx) : 0.f;
        float s = e;
        #pragma unroll
        for (int off = 16; off; off >>= 1) s += __shfl_xor_sync(FULLMASK, s, off);
        if (lane < 10) out[b * 10 + lane] = v - mx - logf(s);
    }
}

// ---------------------------------------------------------------------------
extern "C" void kernel_launch(void* const* d_in, const int* in_sizes, int n_in,
                              void* d_out, int out_size) {
    const float* x   = (const float*)d_in[0];   // [8192,1,28,28]
    const float* w1  = (const float*)d_in[1];   // [16,1,3,3]
    const float* w2  = (const float*)d_in[2];   // [16,16,3,3]
    const float* fcw = (const float*)d_in[3];   // [10,2304]
    float* out = (float*)d_out;                 // [8192,10]

    int batch = in_sizes[0] / 784;

    bnn_prep_kernel<<<1, 768>>>(w1, w2, fcw);
    bnn_kernel<<<batch, 288>>>(x, out);
}

// round 2
// speedup vs baseline: 1.0899x; 1.0899x over previous
#include <cuda_runtime.h>
#include <cstdint>

#define FULLMASK 0xFFFFFFFFu

// -------- packed weight storage (written by prep kernel each launch) --------
__device__ uint16_t           g_lut1[512];  // conv1: 9-bit neighborhood -> 16 channel sign bits
__device__ unsigned long long g_w2[48];     // conv2: [o][kernel_row] 48-bit packed (3 cols x 16 ch)
__device__ uint32_t           g_fcb[720];   // fc:    [k][72 words] sign bits over 2304 inputs

// ---------------------------------------------------------------------------
// Prep kernel: binarize + bit-pack all weights.
// Block 0: conv1 LUT + conv2 pack. Blocks 1..30: fc pack, one warp-ballot per word.
// ---------------------------------------------------------------------------
__global__ void bnn_prep_kernel(const float* __restrict__ w1,
                                const float* __restrict__ w2,
                                const float* __restrict__ fcw) {
    int t = threadIdx.x;
    if (blockIdx.x == 0) {
        __shared__ uint32_t w1p[16];
        if (t < 16) {
            uint32_t b = 0;
            #pragma unroll
            for (int rc = 0; rc < 9; rc++)
                if (w1[t * 9 + rc] > 0.f) b |= (1u << rc);
            w1p[t] = b;
        }
        __syncthreads();
        if (t < 512) {
            uint32_t mask = 0;
            #pragma unroll
            for (int o = 0; o < 16; o++) {
                int m = __popc((uint32_t)t ^ w1p[o]);  // 9 terms; sum=9-2m, never 0
                if (m <= 4) mask |= (1u << o);
            }
            g_lut1[t] = (uint16_t)mask;
        }
        if (t < 48) {
            int o = t / 3, r = t % 3;
            unsigned long long v = 0;
            for (int i = 0; i < 16; i++)
                #pragma unroll
                for (int c = 0; c < 3; c++)
                    if (w2[((o * 16 + i) * 3 + r) * 3 + c] > 0.f)
                        v |= (1ull << (c * 16 + i));
            g_w2[t] = v;
        }
    } else {
        // 30 blocks x 24 warps = 720 words of 32 fc weights each, coalesced
        int wd   = (blockIdx.x - 1) * 24 + (t >> 5);
        int lane = t & 31;
        if (wd < 720) {
            uint32_t m = __ballot_sync(FULLMASK, fcw[wd * 32 + lane] > 0.f);
            if (lane == 0) g_fcb[wd] = m;
        }
    }
}

// ---------------------------------------------------------------------------
// Main kernel: one image per CTA, 288 threads (9 warps).
// ---------------------------------------------------------------------------
__global__ __launch_bounds__(288, 5) void bnn_kernel(const float* __restrict__ x,
                                                     float* __restrict__ out) {
    __shared__ uint32_t           xb[28];        // thresholded input rows
    __shared__ uint16_t           s1m[676];      // conv1 sign masks, 26x26 (bit c = channel)
    __shared__ int8_t             s3s[2304];     // ternary pooled activations [o*144 + p]
    __shared__ uint16_t           lut[512];
    __shared__ unsigned long long w2p[48];
    __shared__ uint32_t           fcb[720];
    __shared__ uint32_t           Pw[72], Mw[72];
    __shared__ int                lg[10];

    const int tid  = threadIdx.x;
    const int warp = tid >> 5;
    const int lane = tid & 31;
    const int b    = blockIdx.x;
    const float* xi = x + (size_t)b * 784;

    // weights -> smem
    if (tid < 256) ((uint32_t*)lut)[tid] = ((const uint32_t*)g_lut1)[tid];
    if (tid < 48)  w2p[tid] = g_w2[tid];
    for (int q = tid; q < 720; q += 288) fcb[q] = g_fcb[q];

    // ---- threshold + bit-pack input (x >= 0.2 -> +1) ----
    for (int row = warp; row < 28; row += 9) {
        int act = (lane < 28);
        float v = act ? xi[row * 28 + lane] : -1.f;
        uint32_t m = __ballot_sync(FULLMASK, act && (v >= 0.2f));
        if (lane == 0) xb[row] = m;
    }
    __syncthreads();

    // ---- conv1 + sign via LUT: 676 output pixels, 16 channels each ----
    for (int p = tid; p < 676; p += 288) {
        int i = p / 26, j = p - i * 26;
        uint32_t b9 = ((xb[i]     >> j) & 7u)
                    | (((xb[i + 1] >> j) & 7u) << 3)
                    | (((xb[i + 2] >> j) & 7u) << 6);
        s1m[p] = lut[b9];
    }
    __syncthreads();

    // ---- conv2 + sign + 2x2 avgpool + sign ----
    // thread = (pooled 2x2 block, pool column dx); all 16 channels per thread.
    // Thread pair (2b, 2b+1) combines its two column-signs via shfl.
    {
        int blk = tid >> 1;            // 0..143 pooled pixel
        int dx  = tid & 1;             // pool column
        int pi = blk / 12, pj = blk - pi * 12;
        int y0 = pi * 2, xcol = pj * 2 + dx;
        unsigned long long P[4];
        #pragma unroll
        for (int rr = 0; rr < 4; rr++) {
            const uint16_t* rowp = &s1m[(y0 + rr) * 26 + xcol];
            unsigned long long m0 = rowp[0], m1 = rowp[1], m2 = rowp[2];
            P[rr] = m0 | (m1 << 16) | (m2 << 32);
        }
        #pragma unroll
        for (int o = 0; o < 16; o++) {
            unsigned long long wr0 = w2p[o * 3 + 0];
            unsigned long long wr1 = w2p[o * 3 + 1];
            unsigned long long wr2 = w2p[o * 3 + 2];
            // mismatches over 144 bits; conv2 sum = 144 - 2m; sign: m<72 -> +1, ==72 -> 0
            int m0 = __popcll(P[0] ^ wr0) + __popcll(P[1] ^ wr1) + __popcll(P[2] ^ wr2);
            int m1 = __popcll(P[1] ^ wr0) + __popcll(P[2] ^ wr1) + __popcll(P[3] ^ wr2);
            int t2 = (m0 < 72) - (m0 > 72) + (m1 < 72) - (m1 > 72);
            int t4 = t2 + __shfl_xor_sync(FULLMASK, t2, 1);
            if (dx == 0) s3s[o * 144 + blk] = (int8_t)((t4 > 0) - (t4 < 0));
        }
    }
    __syncthreads();

    // ---- pack ternary s3 into plus/minus bitmasks (72 words of 2304 bits) ----
    #pragma unroll
    for (int it = 0; it < 8; it++) {
        int v = s3s[it * 288 + tid];
        uint32_t Pm = __ballot_sync(FULLMASK, v > 0);
        uint32_t Mm = __ballot_sync(FULLMASK, v < 0);
        if (lane == 0) { Pw[it * 9 + warp] = Pm; Mw[it * 9 + warp] = Mm; }
    }
    __syncthreads();

    // ---- FC via AND+popcount: warp w -> logit k=w; warp 0 also k=9 ----
    for (int rep = 0; rep < 2; rep++) {
        if (rep == 1 && warp != 0) break;
        int k = (rep == 0) ? warp : 9;
        int acc = 0, c = 0;
        for (int wd = lane; wd < 72; wd += 32) {
            uint32_t p = Pw[wd], m = Mw[wd], wk = fcb[k * 72 + wd];
            acc += __popc(p & wk) - __popc(m & wk);
            c   += __popc(m) - __popc(p);
        }
        #pragma unroll
        for (int off = 16; off; off >>= 1) {
            acc += __shfl_xor_sync(FULLMASK, acc, off);
            c   += __shfl_xor_sync(FULLMASK, c, off);
        }
        if (lane == 0) lg[k] = 2 * acc + c;
    }
    __syncthreads();

    // ---- log_softmax over 10 logits (warp 0) ----
    if (warp == 0) {
        float v = (lane < 10) ? (float)lg[lane] : -3.0e38f;
        float mx = v;
        #pragma unroll
        for (int off = 16; off; off >>= 1) mx = fmaxf(mx, __shfl_xor_sync(FULLMASK, mx, off));
        float e = (lane < 10) ? expf(v - mx) : 0.f;
        float s = e;
        #pragma unroll
        for (int off = 16; off; off >>= 1) s += __shfl_xor_sync(FULLMASK, s, off);
        if (lane < 10) out[b * 10 + lane] = v - mx - logf(s);
    }
}

// ---------------------------------------------------------------------------
extern "C" void kernel_launch(void* const* d_in, const int* in_sizes, int n_in,
                              void* d_out, int out_size) {
    const float* x   = (const float*)d_in[0];   // [8192,1,28,28]
    const float* w1  = (const float*)d_in[1];   // [16,1,3,3]
    const float* w2  = (const float*)d_in[2];   // [16,16,3,3]
    const float* fcw = (const float*)d_in[3];   // [10,2304]
    float* out = (float*)d_out;                 // [8192,10]

    int batch = in_sizes[0] / 784;

    bnn_prep_kernel<<<31, 768>>>(w1, w2, fcw);
    bnn_kernel<<<batch, 288>>>(x, out);
}

// round 4
// speedup vs baseline: 1.2211x; 1.1203x over previous
#include <cuda_runtime.h>
#include <cstdint>

#define FULLMASK 0xFFFFFFFFu

// -------- packed weight storage (written by prep kernel each launch) --------
__device__ uint16_t           g_lut1[512];  // conv1: 9-bit neighborhood -> 16 channel sign bits
__device__ unsigned long long g_w2a[16];    // conv2 dense 144-bit weights: bits [0:64)
__device__ unsigned long long g_w2b[16];    //   bits [64:128)
__device__ uint32_t           g_w2c[16];    //   bits [128:144)
__device__ uint32_t           g_fcb[720];   // fc: [k][72 words] sign bits over 2304 inputs

// ---------------------------------------------------------------------------
// Prep kernel: binarize + bit-pack all weights.
// Block 0: conv1 LUT + conv2 dense pack. Blocks 1..30: fc pack via warp ballot.
// ---------------------------------------------------------------------------
__global__ void bnn_prep_kernel(const float* __restrict__ w1,
                                const float* __restrict__ w2,
                                const float* __restrict__ fcw) {
    int t = threadIdx.x;
    if (blockIdx.x == 0) {
        __shared__ uint32_t w1p[16];
        if (t < 16) {
            uint32_t b = 0;
            #pragma unroll
            for (int rc = 0; rc < 9; rc++)
                if (w1[t * 9 + rc] > 0.f) b |= (1u << rc);
            w1p[t] = b;
        }
        __syncthreads();
        if (t < 512) {
            uint32_t mask = 0;
            #pragma unroll
            for (int o = 0; o < 16; o++) {
                int m = __popc((uint32_t)t ^ w1p[o]);  // 9 terms; sum=9-2m, never 0
                if (m <= 4) mask |= (1u << o);
            }
            g_lut1[t] = (uint16_t)mask;
        }
        if (t < 16) {
            // per-kernel-row 48-bit packs: bit (c*16+i) = sign(w2[o][i][r][c])
            unsigned long long r[3];
            #pragma unroll
            for (int rr = 0; rr < 3; rr++) {
                unsigned long long v = 0;
                for (int i = 0; i < 16; i++)
                    #pragma unroll
                    for (int c = 0; c < 3; c++)
                        if (w2[((t * 16 + i) * 3 + rr) * 3 + c] > 0.f)
                            v |= (1ull << (c * 16 + i));
                r[rr] = v;
            }
            // dense 144-bit concatenation r0|r1|r2
            g_w2a[t] = r[0] | (r[1] << 48);
            g_w2b[t] = (r[1] >> 16) | (r[2] << 32);
            g_w2c[t] = (uint32_t)(r[2] >> 32);
        }
    } else {
        // 30 blocks x 24 warps = 720 words of 32 fc weights each, coalesced
        int wd   = (blockIdx.x - 1) * 24 + (t >> 5);
        int lane = t & 31;
        if (wd < 720) {
            uint32_t m = __ballot_sync(FULLMASK, fcw[wd * 32 + lane] > 0.f);
            if (lane == 0) g_fcb[wd] = m;
        }
    }
}

// ---------------------------------------------------------------------------
// Main kernel: one image per CTA, 288 threads (9 warps).
// ---------------------------------------------------------------------------
__global__ __launch_bounds__(288, 5) void bnn_kernel(const float* __restrict__ x,
                                                     float* __restrict__ out) {
    __shared__ uint32_t           xb[28];        // thresholded input rows
    __shared__ uint16_t           s1m[676];      // conv1 sign masks, 26x26 (bit c = channel)
    __shared__ int8_t             s3s[2304];     // ternary pooled activations [o*144 + p]
    __shared__ uint16_t           lut[512];
    __shared__ unsigned long long w2a[16], w2b[16];
    __shared__ uint32_t           w2c[16];
    __shared__ uint32_t           fcb[720];
    __shared__ uint32_t           Pw[72], Mw[72];
    __shared__ int                lg[10];

    const int tid  = threadIdx.x;
    const int warp = tid >> 5;
    const int lane = tid & 31;
    const int b    = blockIdx.x;
    const float* xi = x + (size_t)b * 784;

    // weights -> smem
    if (tid < 256) ((uint32_t*)lut)[tid] = ((const uint32_t*)g_lut1)[tid];
    if (tid >= 256 && tid < 272) {
        int o = tid - 256;
        w2a[o] = g_w2a[o]; w2b[o] = g_w2b[o]; w2c[o] = g_w2c[o];
    }
    for (int q = tid; q < 720; q += 288) fcb[q] = g_fcb[q];

    // ---- threshold + bit-pack input (x >= 0.2 -> +1) ----
    for (int row = warp; row < 28; row += 9) {
        int act = (lane < 28);
        float v = act ? xi[row * 28 + lane] : -1.f;
        uint32_t m = __ballot_sync(FULLMASK, act && (v >= 0.2f));
        if (lane == 0) xb[row] = m;
    }
    __syncthreads();

    // ---- conv1 + sign via LUT: 676 output pixels, 16 channels each ----
    for (int p = tid; p < 676; p += 288) {
        int i = p / 26, j = p - i * 26;
        uint32_t b9 = ((xb[i]     >> j) & 7u)
                    | (((xb[i + 1] >> j) & 7u) << 3)
                    | (((xb[i + 2] >> j) & 7u) << 6);
        s1m[p] = lut[b9];
    }
    __syncthreads();

    // ---- conv2 + sign + 2x2 avgpool + sign (dense 144-bit XNOR popcount) ----
    // thread = (pooled 2x2 block, pool column dx); all 16 channels per thread.
    {
        int blk = tid >> 1;            // 0..143 pooled pixel
        int dx  = tid & 1;             // pool column
        int pi = blk / 12, pj = blk - pi * 12;
        int y0 = pi * 2, xcol = pj * 2 + dx;
        unsigned long long R[4];       // 48-bit row windows (3 cols x 16 ch)
        #pragma unroll
        for (int rr = 0; rr < 4; rr++) {
            const uint16_t* rowp = &s1m[(y0 + rr) * 26 + xcol];
            unsigned long long m0 = rowp[0], m1 = rowp[1], m2 = rowp[2];
            R[rr] = m0 | (m1 << 16) | (m2 << 32);
        }
        // dense 144-bit windows for the two pool rows
        unsigned long long A0 = R[0] | (R[1] << 48);
        unsigned long long A1 = (R[1] >> 16) | (R[2] << 32);
        uint32_t           A2 = (uint32_t)(R[2] >> 32);
        unsigned long long B0 = R[1] | (R[2] << 48);
        unsigned long long B1 = (R[2] >> 16) | (R[3] << 32);
        uint32_t           B2 = (uint32_t)(R[3] >> 32);
        #pragma unroll
        for (int o = 0; o < 16; o++) {
            unsigned long long wa = w2a[o], wb = w2b[o];
            uint32_t           wc = w2c[o];
            // mismatches over 144 bits; conv2 sum = 144 - 2m; sign: m<72 -> +1, ==72 -> 0
            int m0 = __popcll(A0 ^ wa) + __popcll(A1 ^ wb) + __popc(A2 ^ wc);
            int m1 = __popcll(B0 ^ wa) + __popcll(B1 ^ wb) + __popc(B2 ^ wc);
            int t2 = (m0 < 72) - (m0 > 72) + (m1 < 72) - (m1 > 72);
            int t4 = t2 + __shfl_xor_sync(FULLMASK, t2, 1);
            if (dx == 0) s3s[o * 144 + blk] = (int8_t)((t4 > 0) - (t4 < 0));
        }
    }
    __syncthreads();

    // ---- pack ternary s3 into plus/minus bitmasks (72 words of 2304 bits) ----
    #pragma unroll
    for (int it = 0; it < 8; it++) {
        int v = s3s[it * 288 + tid];
        uint32_t Pm = __ballot_sync(FULLMASK, v > 0);
        uint32_t Mm = __ballot_sync(FULLMASK, v < 0);
        if (lane == 0) { Pw[it * 9 + warp] = Pm; Mw[it * 9 + warp] = Mm; }
    }
    __syncthreads();

    // ---- FC via AND+popcount: warp w -> logit k=w; warp 0 also k=9 ----
    for (int rep = 0; rep < 2; rep++) {
        if (rep == 1 && warp != 0) break;
        int k = (rep == 0) ? warp : 9;
        int acc = 0, c = 0;
        for (int wd = lane; wd < 72; wd += 32) {
            uint32_t p = Pw[wd], m = Mw[wd], wk = fcb[k * 72 + wd];
            acc += __popc(p & wk) - __popc(m & wk);
            c   += __popc(m) - __popc(p);
        }
        #pragma unroll
        for (int off = 16; off; off >>= 1) {
            acc += __shfl_xor_sync(FULLMASK, acc, off);
            c   += __shfl_xor_sync(FULLMASK, c, off);
        }
        if (lane == 0) lg[k] = 2 * acc + c;
    }
    __syncthreads();

    // ---- log_softmax over 10 logits (warp 0) ----
    if (warp == 0) {
        float v = (lane < 10) ? (float)lg[lane] : -3.0e38f;
        float mx = v;
        #pragma unroll
        for (int off = 16; off; off >>= 1) mx = fmaxf(mx, __shfl_xor_sync(FULLMASK, mx, off));
        float e = (lane < 10) ? expf(v - mx) : 0.f;
        float s = e;
        #pragma unroll
        for (int off = 16; off; off >>= 1) s += __shfl_xor_sync(FULLMASK, s, off);
        if (lane < 10) out[b * 10 + lane] = v - mx - logf(s);
    }
}

// ---------------------------------------------------------------------------
extern "C" void kernel_launch(void* const* d_in, const int* in_sizes, int n_in,
                              void* d_out, int out_size) {
    const float* x   = (const float*)d_in[0];   // [8192,1,28,28]
    const float* w1  = (const float*)d_in[1];   // [16,1,3,3]
    const float* w2  = (const float*)d_in[2];   // [16,16,3,3]
    const float* fcw = (const float*)d_in[3];   // [10,2304]
    float* out = (float*)d_out;                 // [8192,10]

    int batch = in_sizes[0] / 784;

    bnn_prep_kernel<<<31, 768>>>(w1, w2, fcw);
    bnn_kernel<<<batch, 288>>>(x, out);
}

// round 6
// speedup vs baseline: 1.5665x; 1.2829x over previous
#include <cuda_runtime.h>
#include <cstdint>

#define FULLMASK 0xFFFFFFFFu

// -------- precomputed tables (__device__ globals; written by prep kernels) --------
__device__ uint16_t           g_lut1[512];      // 9-bit patch -> 16 conv1 sign bits
__device__ unsigned long long g_w2col[48];      // [c*16+o] conv2 col pack: bit r*16+i
__device__ uint32_t           g_fcb[720];       // fc sign bits [k][72 words]
__device__ uint4              g_lut2[3 * 32768];// [c][15-bit patch] -> 16 bytes: per-channel
                                                //   mismatch count (0..48) of strip c

// ---------------------------------------------------------------------------
// prep1: conv1 LUT, conv2 column packs, fc bit-pack.
// ---------------------------------------------------------------------------
__global__ void bnn_prep1(const float* __restrict__ w1,
                          const float* __restrict__ w2,
                          const float* __restrict__ fcw) {
    int t = threadIdx.x;
    if (blockIdx.x == 0) {
        __shared__ uint32_t w1p[16];
        if (t < 16) {
            uint32_t b = 0;
            #pragma unroll
            for (int rc = 0; rc < 9; rc++)
                if (w1[t * 9 + rc] > 0.f) b |= (1u << rc);
            w1p[t] = b;
        }
        __syncthreads();
        if (t < 512) {
            uint32_t mask = 0;
            #pragma unroll
            for (int o = 0; o < 16; o++) {
                int m = __popc((uint32_t)t ^ w1p[o]);  // 9 odd terms; never 0
                if (m <= 4) mask |= (1u << o);
            }
            g_lut1[t] = (uint16_t)mask;
        }
        if (t < 48) {
            int c = t >> 4, o = t & 15;
            unsigned long long v = 0;
            for (int r = 0; r < 3; r++)
                #pragma unroll
                for (int i = 0; i < 16; i++)
                    if (w2[((o * 16 + i) * 3 + r) * 3 + c] > 0.f)
                        v |= (1ull << (r * 16 + i));
            g_w2col[t] = v;
        }
    } else {
        // 30 blocks x 24 warps: fc pack via coalesced warp ballot
        int wd   = (blockIdx.x - 1) * 24 + (t >> 5);
        int lane = t & 31;
        if (wd < 720) {
            uint32_t m = __ballot_sync(FULLMASK, fcw[wd * 32 + lane] > 0.f);
            if (lane == 0) g_fcb[wd] = m;
        }
    }
}

// ---------------------------------------------------------------------------
// prep2: build conv1+conv2 fused strip LUT. 384 blocks x 256 threads.
// Entry (c, idx15): idx bit (r*3+cc) = input[y+r][x+c+cc]. Byte o = mismatch
// count of the 48-bit strip (3 s1-rows x 16 ch) vs weight column c of channel o.
// ---------------------------------------------------------------------------
__global__ void bnn_prep2() {
    int e   = blockIdx.x * 256 + threadIdx.x;   // 0..98303
    int c   = e >> 15;
    int idx = e & 32767;
    unsigned long long V = (unsigned long long)g_lut1[idx & 511]
                         | ((unsigned long long)g_lut1[(idx >> 3) & 511] << 16)
                         | ((unsigned long long)g_lut1[(idx >> 6) & 511] << 32);
    uint32_t w[4];
    #pragma unroll
    for (int g = 0; g < 4; g++) {
        uint32_t word = 0;
        #pragma unroll
        for (int j = 0; j < 4; j++) {
            int o = g * 4 + j;
            int m = __popcll(V ^ g_w2col[c * 16 + o]);   // 0..48
            word |= (uint32_t)m << (8 * j);
        }
        w[g] = word;
    }
    g_lut2[e] = make_uint4(w[0], w[1], w[2], w[3]);
}

// ---------------------------------------------------------------------------
// Main kernel: one image per CTA, 288 threads (9 warps).
// ---------------------------------------------------------------------------
__global__ __launch_bounds__(288, 5) void bnn_kernel(const float* __restrict__ x,
                                                     float* __restrict__ out) {
    __shared__ uint32_t xb[28];      // thresholded input rows (bit j = col j)
    __shared__ uint32_t s3c[576];    // class bytes at [p*16+o]: 0=neg,1=zero,2=pos
    __shared__ uint32_t Pw[72], Mw[72];
    __shared__ int      lg[10];

    const int tid  = threadIdx.x;
    const int warp = tid >> 5;
    const int lane = tid & 31;
    const int b    = blockIdx.x;
    const float* xi = x + (size_t)b * 784;

    // ---- threshold + bit-pack input (x >= 0.2 -> +1) ----
    for (int row = warp; row < 28; row += 9) {
        int act = (lane < 28);
        float v = act ? xi[row * 28 + lane] : -1.f;
        uint32_t m = __ballot_sync(FULLMASK, act && (v >= 0.2f));
        if (lane == 0) xb[row] = m;
    }
    __syncthreads();

    // ---- conv1+conv2+sign via strip LUT, then 2x2 avgpool + sign ----
    // thread = (pooled block, pool column dx); computes the dy-pair of conv2
    // positions (y0, xcol), (y0+1, xcol) for ALL 16 channels.
    {
        int blk = tid >> 1;                 // 0..143
        int dx  = tid & 1;
        int pi = blk / 12, pj = blk - pi * 12;
        int y0 = pi * 2, xcol = pj * 2 + dx;

        uint32_t r0 = xb[y0],     r1 = xb[y0 + 1], r2 = xb[y0 + 2];
        uint32_t r3 = xb[y0 + 3], r4 = xb[y0 + 4], r5 = xb[y0 + 5];

        uint32_t a0[4], a1[4];              // per-channel mismatch sums (byte lanes)
        #pragma unroll
        for (int c = 0; c < 3; c++) {
            int sh = xcol + c;
            uint32_t c0 = (r0 >> sh) & 7u, c1 = (r1 >> sh) & 7u, c2 = (r2 >> sh) & 7u;
            uint32_t c3 = (r3 >> sh) & 7u, c4 = (r4 >> sh) & 7u, c5 = (r5 >> sh) & 7u;
            uint32_t i0 = c0 | (c1 << 3) | (c2 << 6) | (c3 << 9) | (c4 << 12);
            uint32_t i1 = (i0 >> 3) | (c5 << 12);
            uint4 e0 = g_lut2[(c << 15) + i0];
            uint4 e1 = g_lut2[(c << 15) + i1];
            if (c == 0) {
                a0[0] = e0.x; a0[1] = e0.y; a0[2] = e0.z; a0[3] = e0.w;
                a1[0] = e1.x; a1[1] = e1.y; a1[2] = e1.z; a1[3] = e1.w;
            } else {
                a0[0] += e0.x; a0[1] += e0.y; a0[2] += e0.z; a0[3] += e0.w;
                a1[0] += e1.x; a1[1] += e1.y; a1[2] += e1.z; a1[3] += e1.w;
            }   // byte lanes: 3*48 = 144 < 256, no carry
        }
        const uint32_t M7 = 0x80808080u;
        #pragma unroll
        for (int g = 0; g < 4; g++) {
            uint32_t m0 = a0[g], m1 = a1[g];      // bytes in [0,144]; sign = sgn(144-2m)
            uint32_t ge0 = (m0 + 0x38383838u);    // bit7: m >= 72
            uint32_t gt0 = (m0 + 0x37373737u);    // bit7: m >  72
            uint32_t ge1 = (m1 + 0x38383838u);
            uint32_t gt1 = (m1 + 0x37373737u);
            uint32_t pos = (((~ge0) & M7) >> 7) + (((~ge1) & M7) >> 7);  // bytes 0..2
            uint32_t neg = ((gt0 & M7) >> 7) + ((gt1 & M7) >> 7);
            uint32_t t   = pos + 0x02020202u - neg;                      // biased by 2
            uint32_t t4b = t + __shfl_xor_sync(FULLMASK, t, 1);          // bytes 0..8, bias 4
            uint32_t gtm = (t4b + 0x7B7B7B7Bu) & M7;                     // t4 > 0
            uint32_t gem = (t4b + 0x7C7C7C7Cu) & M7;                     // t4 >= 0
            uint32_t cls = (gtm >> 7) + (0x01010101u - (((~gem) & M7) >> 7));
            if (dx == 0) s3c[blk * 4 + g] = cls;  // byte o: 2=pos,1=zero,0=neg
        }
    }
    __syncthreads();

    // ---- pack ternary s3 into plus/minus bitmasks (fc flatten order o*144+p) ----
    {
        const uint8_t* s3b = (const uint8_t*)s3c;
        int o0 = tid / 144;                 // 0 or 1
        int p  = tid - o0 * 144;
        int base = p * 16 + o0;
        #pragma unroll
        for (int it = 0; it < 8; it++) {
            uint32_t v = s3b[base + 2 * it];
            uint32_t Pm = __ballot_sync(FULLMASK, v == 2u);
            uint32_t Mm = __ballot_sync(FULLMASK, v == 0u);
            if (lane == 0) { Pw[it * 9 + warp] = Pm; Mw[it * 9 + warp] = Mm; }
        }
    }
    __syncthreads();

    // ---- FC via AND+popcount (weights from L2-resident g_fcb) ----
    for (int rep = 0; rep < 2; rep++) {
        if (rep == 1 && warp != 0) break;
        int k = (rep == 0) ? warp : 9;
        int acc = 0, c = 0;
        for (int wd = lane; wd < 72; wd += 32) {
            uint32_t p = Pw[wd], m = Mw[wd], wk = g_fcb[k * 72 + wd];
            acc += __popc(p & wk) - __popc(m & wk);
            c   += __popc(m) - __popc(p);
        }
        #pragma unroll
        for (int off = 16; off; off >>= 1) {
            acc += __shfl_xor_sync(FULLMASK, acc, off);
            c   += __shfl_xor_sync(FULLMASK, c, off);
        }
        if (lane == 0) lg[k] = 2 * acc + c;
    }
    __syncthreads();

    // ---- log_softmax over 10 logits ----
    if (warp == 0) {
        float v = (lane < 10) ? (float)lg[lane] : -3.0e38f;
        float mx = v;
        #pragma unroll
        for (int off = 16; off; off >>= 1) mx = fmaxf(mx, __shfl_xor_sync(FULLMASK, mx, off));
        float e = (lane < 10) ? expf(v - mx) : 0.f;
        float s = e;
        #pragma unroll
        for (int off = 16; off; off >>= 1) s += __shfl_xor_sync(FULLMASK, s, off);
        if (lane < 10) out[b * 10 + lane] = v - mx - logf(s);
    }
}

// ---------------------------------------------------------------------------
extern "C" void kernel_launch(void* const* d_in, const int* in_sizes, int n_in,
                              void* d_out, int out_size) {
    const float* x   = (const float*)d_in[0];   // [8192,1,28,28]
    const float* w1  = (const float*)d_in[1];   // [16,1,3,3]
    const float* w2  = (const float*)d_in[2];   // [16,16,3,3]
    const float* fcw = (const float*)d_in[3];   // [10,2304]
    float* out = (float*)d_out;                 // [8192,10]

    int batch = in_sizes[0] / 784;

    bnn_prep1<<<31, 768>>>(w1, w2, fcw);
    bnn_prep2<<<384, 256>>>();
    bnn_kernel<<<batch, 288>>>(x, out);
}

// round 7
// speedup vs baseline: 1.5676x; 1.0007x over previous
#include <cuda_runtime.h>
#include <cstdint>

#define FULLMASK 0xFFFFFFFFu

// -------- precomputed tables (__device__ globals; written by prep kernel) --------
__device__ uint32_t g_fcb[720];        // fc sign bits [k][72 words]
__device__ uint4    g_lut2[3 * 32768]; // [c][15-bit patch] -> 16 bytes: per-channel
                                       //   mismatch count (0..48) of strip c

// ---------------------------------------------------------------------------
// Single prep kernel, 474 blocks x 256 threads.
// Blocks 0..383: build g_lut2 (each block recomputes lut1/w2col locally).
// Blocks 384..473: fc bit-pack via coalesced warp ballot (8 words/block).
// ---------------------------------------------------------------------------
__global__ void bnn_prep(const float* __restrict__ w1,
                         const float* __restrict__ w2,
                         const float* __restrict__ fcw) {
    const int t = threadIdx.x;
    if (blockIdx.x < 384) {
        __shared__ uint32_t           w1p[16];
        __shared__ uint16_t           lut1[512];
        __shared__ unsigned long long w2c[48];
        if (t < 16) {
            uint32_t b = 0;
            #pragma unroll
            for (int rc = 0; rc < 9; rc++)
                if (w1[t * 9 + rc] > 0.f) b |= (1u << rc);
            w1p[t] = b;
        }
        if (t < 48) {   // conv2 column packs: bit r*16+i = sign(w2[o][i][r][c])
            int c = t >> 4, o = t & 15;
            unsigned long long v = 0;
            for (int r = 0; r < 3; r++)
                #pragma unroll
                for (int i = 0; i < 16; i++)
                    if (w2[((o * 16 + i) * 3 + r) * 3 + c] > 0.f)
                        v |= (1ull << (r * 16 + i));
            w2c[t] = v;
        }
        __syncthreads();
        for (int e = t; e < 512; e += 256) {
            uint32_t mask = 0;
            #pragma unroll
            for (int o = 0; o < 16; o++) {
                int m = __popc((uint32_t)e ^ w1p[o]);  // 9 odd terms; never 0
                if (m <= 4) mask |= (1u << o);
            }
            lut1[e] = (uint16_t)mask;
        }
        __syncthreads();
        // entry (c, idx15): idx bit (r*3+cc) = input[y+r][x+c+cc]
        int c   = blockIdx.x >> 7;                    // 0..2
        int idx = ((blockIdx.x & 127) << 8) + t;      // 0..32767
        unsigned long long V = (unsigned long long)lut1[idx & 511]
                             | ((unsigned long long)lut1[(idx >> 3) & 511] << 16)
                             | ((unsigned long long)lut1[(idx >> 6) & 511] << 32);
        uint32_t w[4];
        #pragma unroll
        for (int g = 0; g < 4; g++) {
            uint32_t word = 0;
            #pragma unroll
            for (int j = 0; j < 4; j++) {
                int m = __popcll(V ^ w2c[c * 16 + g * 4 + j]);  // 0..48
                word |= (uint32_t)m << (8 * j);
            }
            w[g] = word;
        }
        g_lut2[(c << 15) + idx] = make_uint4(w[0], w[1], w[2], w[3]);
    } else {
        int wd   = (blockIdx.x - 384) * 8 + (t >> 5);  // 0..719
        int lane = t & 31;
        uint32_t m = __ballot_sync(FULLMASK, fcw[wd * 32 + lane] > 0.f);
        if (lane == 0) g_fcb[wd] = m;
    }
}

// ---------------------------------------------------------------------------
// Main kernel: one image per CTA, 288 threads (9 warps).
// ---------------------------------------------------------------------------
__global__ __launch_bounds__(288, 6) void bnn_kernel(const float* __restrict__ x,
                                                     float* __restrict__ out) {
    __shared__ uint32_t xb[28];      // thresholded input rows (bit j = col j)
    __shared__ uint32_t s3c[576];    // class bytes at [p*16+o]: 0=neg,1=zero,2=pos
    __shared__ uint32_t Pw[72], Mw[72];
    __shared__ int      lg[10];

    const int tid  = threadIdx.x;
    const int warp = tid >> 5;
    const int lane = tid & 31;
    const int b    = blockIdx.x;
    const float* xi = x + (size_t)b * 784;

    // ---- threshold + bit-pack input (x >= 0.2 -> +1) ----
    for (int row = warp; row < 28; row += 9) {
        int act = (lane < 28);
        float v = act ? xi[row * 28 + lane] : -1.f;
        uint32_t m = __ballot_sync(FULLMASK, act && (v >= 0.2f));
        if (lane == 0) xb[row] = m;
    }
    __syncthreads();

    // ---- conv1+conv2+sign via strip LUT, then 2x2 avgpool + sign ----
    // thread = (pooled block, pool column dx); the vertical pair of conv2
    // positions (y0, xcol), (y0+1, xcol) for ALL 16 channels.
    {
        int blk = tid >> 1;                 // 0..143
        int dx  = tid & 1;
        int pi = blk / 12, pj = blk - pi * 12;
        int y0 = pi * 2, xcol = pj * 2 + dx;

        uint32_t r0 = xb[y0],     r1 = xb[y0 + 1], r2 = xb[y0 + 2];
        uint32_t r3 = xb[y0 + 3], r4 = xb[y0 + 4], r5 = xb[y0 + 5];

        uint32_t a0[4], a1[4];              // per-channel mismatch sums (byte lanes)
        #pragma unroll
        for (int c = 0; c < 3; c++) {
            int sh = xcol + c;
            uint32_t c0 = (r0 >> sh) & 7u, c1 = (r1 >> sh) & 7u, c2 = (r2 >> sh) & 7u;
            uint32_t c3 = (r3 >> sh) & 7u, c4 = (r4 >> sh) & 7u, c5 = (r5 >> sh) & 7u;
            uint32_t i0 = c0 | (c1 << 3) | (c2 << 6) | (c3 << 9) | (c4 << 12);
            uint32_t i1 = (i0 >> 3) | (c5 << 12);
            uint4 e0 = g_lut2[(c << 15) + i0];
            uint4 e1 = g_lut2[(c << 15) + i1];
            if (c == 0) {
                a0[0] = e0.x; a0[1] = e0.y; a0[2] = e0.z; a0[3] = e0.w;
                a1[0] = e1.x; a1[1] = e1.y; a1[2] = e1.z; a1[3] = e1.w;
            } else {
                a0[0] += e0.x; a0[1] += e0.y; a0[2] += e0.z; a0[3] += e0.w;
                a1[0] += e1.x; a1[1] += e1.y; a1[2] += e1.z; a1[3] += e1.w;
            }   // byte lanes: 3*48 = 144 < 256, no carry
        }
        const uint32_t M7 = 0x80808080u;
        #pragma unroll
        for (int g = 0; g < 4; g++) {
            uint32_t m0 = a0[g], m1 = a1[g];      // bytes in [0,144]; sign = sgn(144-2m)
            uint32_t ge0 = (m0 + 0x38383838u);    // bit7: m >= 72
            uint32_t gt0 = (m0 + 0x37373737u);    // bit7: m >  72
            uint32_t ge1 = (m1 + 0x38383838u);
            uint32_t gt1 = (m1 + 0x37373737u);
            uint32_t pos = (((~ge0) & M7) >> 7) + (((~ge1) & M7) >> 7);  // bytes 0..2
            uint32_t neg = ((gt0 & M7) >> 7) + ((gt1 & M7) >> 7);
            uint32_t t   = pos + 0x02020202u - neg;                      // biased by 2
            uint32_t t4b = t + __shfl_xor_sync(FULLMASK, t, 1);          // bytes 0..8, bias 4
            uint32_t gtm = (t4b + 0x7B7B7B7Bu) & M7;                     // t4 > 0
            uint32_t gem = (t4b + 0x7C7C7C7Cu) & M7;                     // t4 >= 0
            uint32_t cls = (gtm >> 7) + (0x01010101u - (((~gem) & M7) >> 7));
            if (dx == 0) s3c[blk * 4 + g] = cls;  // byte o: 2=pos,1=zero,0=neg
        }
    }
    __syncthreads();

    // ---- pack ternary s3 into plus/minus bitmasks (fc flatten order o*144+p) ----
    {
        const uint8_t* s3b = (const uint8_t*)s3c;
        int o0 = tid / 144;                 // 0 or 1
        int p  = tid - o0 * 144;
        int base = p * 16 + o0;
        #pragma unroll
        for (int it = 0; it < 8; it++) {
            uint32_t v = s3b[base + 2 * it];
            uint32_t Pm = __ballot_sync(FULLMASK, v == 2u);
            uint32_t Mm = __ballot_sync(FULLMASK, v == 0u);
            if (lane == 0) { Pw[it * 9 + warp] = Pm; Mw[it * 9 + warp] = Mm; }
        }
    }
    __syncthreads();

    // ---- FC via AND+popcount (weights from L2-resident g_fcb) ----
    for (int rep = 0; rep < 2; rep++) {
        if (rep == 1 && warp != 0) break;
        int k = (rep == 0) ? warp : 9;
        int acc = 0, c = 0;
        for (int wd = lane; wd < 72; wd += 32) {
            uint32_t p = Pw[wd], m = Mw[wd], wk = g_fcb[k * 72 + wd];
            acc += __popc(p & wk) - __popc(m & wk);
            c   += __popc(m) - __popc(p);
        }
        #pragma unroll
        for (int off = 16; off; off >>= 1) {
            acc += __shfl_xor_sync(FULLMASK, acc, off);
            c   += __shfl_xor_sync(FULLMASK, c, off);
        }
        if (lane == 0) lg[k] = 2 * acc + c;
    }
    __syncthreads();

    // ---- log_softmax over 10 logits ----
    if (warp == 0) {
        float v = (lane < 10) ? (float)lg[lane] : -3.0e38f;
        float mx = v;
        #pragma unroll
        for (int off = 16; off; off >>= 1) mx = fmaxf(mx, __shfl_xor_sync(FULLMASK, mx, off));
        float e = (lane < 10) ? expf(v - mx) : 0.f;
        float s = e;
        #pragma unroll
        for (int off = 16; off; off >>= 1) s += __shfl_xor_sync(FULLMASK, s, off);
        if (lane < 10) out[b * 10 + lane] = v - mx - logf(s);
    }
}

// ---------------------------------------------------------------------------
extern "C" void kernel_launch(void* const* d_in, const int* in_sizes, int n_in,
                              void* d_out, int out_size) {
    const float* x   = (const float*)d_in[0];   // [8192,1,28,28]
    const float* w1  = (const float*)d_in[1];   // [16,1,3,3]
    const float* w2  = (const float*)d_in[2];   // [16,16,3,3]
    const float* fcw = (const float*)d_in[3];   // [10,2304]
    float* out = (float*)d_out;                 // [8192,10]

    int batch = in_sizes[0] / 784;

    bnn_prep<<<474, 256>>>(w1, w2, fcw);
    bnn_kernel<<<batch, 288>>>(x, out);
}

// round 8
// speedup vs baseline: 1.6988x; 1.0837x over previous
#include <cuda_runtime.h>
#include <cstdint>

#define FULLMASK 0xFFFFFFFFu

// -------- precomputed tables (__device__ globals) --------
__device__ uint32_t g_fcb[720];       // fc sign bits [k][72 words]
__device__ uint4    g_sc[3 * 32768];  // col-major strip tables: [c][idx15] -> 16B
                                      //   per-channel mismatch (0..48) of strip c
__device__ uint4    g_T01[1 << 20];   // [20-bit patch: 4 cols x 5 rows, col-major]
                                      //   -> per-channel (m_c0 + m_c1), 0..96

// ---------------------------------------------------------------------------
// prep_a: build col-major strip tables + fc bit-pack. 474 blocks x 256 thr.
// idx15 layout: bits [5c..5c+5) = column c, bit k within = patch row k.
// ---------------------------------------------------------------------------
__global__ void bnn_prep_a(const float* __restrict__ w1,
                           const float* __restrict__ w2,
                           const float* __restrict__ fcw) {
    const int t = threadIdx.x;
    if (blockIdx.x < 384) {
        __shared__ uint32_t           w1p[16];
        __shared__ uint16_t           lut1[512];
        __shared__ unsigned long long w2c[48];
        if (t < 16) {
            uint32_t b = 0;
            #pragma unroll
            for (int rc = 0; rc < 9; rc++)
                if (w1[t * 9 + rc] > 0.f) b |= (1u << rc);
            w1p[t] = b;
        }
        if (t < 48) {   // bit r*16+i = sign(w2[o][i][r][c])
            int c = t >> 4, o = t & 15;
            unsigned long long v = 0;
            for (int r = 0; r < 3; r++)
                #pragma unroll
                for (int i = 0; i < 16; i++)
                    if (w2[((o * 16 + i) * 3 + r) * 3 + c] > 0.f)
                        v |= (1ull << (r * 16 + i));
            w2c[t] = v;
        }
        __syncthreads();
        for (int e = t; e < 512; e += 256) {
            uint32_t mask = 0;
            #pragma unroll
            for (int o = 0; o < 16; o++) {
                int m = __popc((uint32_t)e ^ w1p[o]);  // 9 odd terms; never 0
                if (m <= 4) mask |= (1u << o);
            }
            lut1[e] = (uint16_t)mask;
        }
        __syncthreads();
        int c   = blockIdx.x >> 7;                 // 0..2 (weight column)
        int idx = ((blockIdx.x & 127) << 8) + t;   // 15-bit col-major patch
        uint32_t col0 = idx & 31, col1 = (idx >> 5) & 31, col2 = (idx >> 10) & 31;
        unsigned long long V = 0;   // s1 sign masks rows 0..2 (bit r*16+i)
        #pragma unroll
        for (int r = 0; r < 3; r++) {
            uint32_t b0 = (col0 >> r) & 7u, b1 = (col1 >> r) & 7u, b2 = (col2 >> r) & 7u;
            uint32_t i9 = ((b0 & 1) | ((b0 & 2) << 2) | ((b0 & 4) << 4))
                        | (((b1 & 1) | ((b1 & 2) << 2) | ((b1 & 4) << 4)) << 1)
                        | (((b2 & 1) | ((b2 & 2) << 2) | ((b2 & 4) << 4)) << 2);
            V |= (unsigned long long)lut1[i9] << (16 * r);
        }
        uint32_t w[4];
        #pragma unroll
        for (int g = 0; g < 4; g++) {
            uint32_t word = 0;
            #pragma unroll
            for (int j = 0; j < 4; j++) {
                int m = __popcll(V ^ w2c[c * 16 + g * 4 + j]);  // 0..48
                word |= (uint32_t)m << (8 * j);
            }
            w[g] = word;
        }
        g_sc[(c << 15) + idx] = make_uint4(w[0], w[1], w[2], w[3]);
    } else {
        int wd   = (blockIdx.x - 384) * 8 + (t >> 5);  // 0..719
        int lane = t & 31;
        uint32_t m = __ballot_sync(FULLMASK, fcw[wd * 32 + lane] > 0.f);
        if (lane == 0) g_fcb[wd] = m;
    }
}

// ---------------------------------------------------------------------------
// prep_b: T01[p] = Sc0[cols 0-2] + Sc1[cols 1-3]. Fully coalesced.
// ---------------------------------------------------------------------------
__global__ void bnn_prep_b() {
    int p = blockIdx.x * 256 + threadIdx.x;        // 20-bit patch index
    uint4 a = g_sc[p & 32767];
    uint4 b = g_sc[32768 + (p >> 5)];
    // byte lanes <= 48+48 = 96: carry-free word adds
    g_T01[p] = make_uint4(a.x + b.x, a.y + b.y, a.z + b.z, a.w + b.w);
}

// ---------------------------------------------------------------------------
// Main kernel: one image per CTA, 288 threads (9 warps).
// ---------------------------------------------------------------------------
__global__ __launch_bounds__(288, 5) void bnn_kernel(const float* __restrict__ x,
                                                     float* __restrict__ out) {
    __shared__ uint32_t xb[28];      // row bitmaps (bit j = col j)
    __shared__ uint32_t xcol[28];    // col bitmaps (bit r = row r)
    __shared__ uint32_t s3c[576];    // class bytes [p*16+o]: 0=neg,1=zero,2=pos
    __shared__ uint32_t Pw[72], Mw[72];
    __shared__ int      lg[10];

    const int tid  = threadIdx.x;
    const int warp = tid >> 5;
    const int lane = tid & 31;
    const int b    = blockIdx.x;
    const float* xi = x + (size_t)b * 784;

    // ---- threshold + bit-pack rows (x >= 0.2 -> +1) ----
    for (int row = warp; row < 28; row += 9) {
        int act = (lane < 28);
        float v = act ? xi[row * 28 + lane] : -1.f;
        uint32_t m = __ballot_sync(FULLMASK, act && (v >= 0.2f));
        if (lane == 0) xb[row] = m;
    }
    __syncthreads();

    // ---- transpose to column bitmaps via ballots ----
    for (int col = warp; col < 28; col += 9) {
        uint32_t bit = (lane < 28) ? ((xb[lane] >> col) & 1u) : 0u;
        uint32_t m = __ballot_sync(FULLMASK, bit);
        if (lane == 0) xcol[col] = m;
    }
    __syncthreads();

    // ---- conv1+conv2+sign via 2 fused-table gathers per output, pool + sign --
    // thread = (pooled block, pool column dx): vertical output pair, 16 ch.
    {
        int blk = tid >> 1;                 // 0..143
        int dx  = tid & 1;
        int pi = blk / 12, pj = blk - pi * 12;
        int y0 = pi * 2, x0 = pj * 2 + dx;

        uint32_t c6_0 = (xcol[x0]     >> y0) & 63u;
        uint32_t c6_1 = (xcol[x0 + 1] >> y0) & 63u;
        uint32_t c6_2 = (xcol[x0 + 2] >> y0) & 63u;
        uint32_t c6_3 = (xcol[x0 + 3] >> y0) & 63u;
        uint32_t c6_4 = (xcol[x0 + 4] >> y0) & 63u;

        uint32_t iA0 = (c6_0 & 31) | ((c6_1 & 31) << 5) | ((c6_2 & 31) << 10) | ((c6_3 & 31) << 15);
        uint32_t iB0 = (c6_2 & 31) | ((c6_3 & 31) << 5) | ((c6_4 & 31) << 10);
        uint32_t iA1 = (c6_0 >> 1) | ((c6_1 >> 1) << 5) | ((c6_2 >> 1) << 10) | ((c6_3 >> 1) << 15);
        uint32_t iB1 = (c6_2 >> 1) | ((c6_3 >> 1) << 5) | ((c6_4 >> 1) << 10);

        uint4 eA0 = g_T01[iA0];
        uint4 eB0 = g_sc[2 * 32768 + iB0];
        uint4 eA1 = g_T01[iA1];
        uint4 eB1 = g_sc[2 * 32768 + iB1];

        uint32_t a0[4], a1[4];   // per-channel total mismatch (bytes, 0..144)
        a0[0] = eA0.x + eB0.x; a0[1] = eA0.y + eB0.y; a0[2] = eA0.z + eB0.z; a0[3] = eA0.w + eB0.w;
        a1[0] = eA1.x + eB1.x; a1[1] = eA1.y + eB1.y; a1[2] = eA1.z + eB1.z; a1[3] = eA1.w + eB1.w;

        const uint32_t M7 = 0x80808080u;
        #pragma unroll
        for (int g = 0; g < 4; g++) {
            uint32_t m0 = a0[g], m1 = a1[g];      // sign = sgn(144-2m)
            uint32_t ge0 = (m0 + 0x38383838u);    // bit7: m >= 72
            uint32_t gt0 = (m0 + 0x37373737u);    // bit7: m >  72
            uint32_t ge1 = (m1 + 0x38383838u);
            uint32_t gt1 = (m1 + 0x37373737u);
            uint32_t pos = (((~ge0) & M7) >> 7) + (((~ge1) & M7) >> 7);
            uint32_t neg = ((gt0 & M7) >> 7) + ((gt1 & M7) >> 7);
            uint32_t t   = pos + 0x02020202u - neg;                      // bias 2
            uint32_t t4b = t + __shfl_xor_sync(FULLMASK, t, 1);          // bias 4
            uint32_t gtm = (t4b + 0x7B7B7B7Bu) & M7;                     // t4 > 0
            uint32_t gem = (t4b + 0x7C7C7C7Cu) & M7;                     // t4 >= 0
            uint32_t cls = (gtm >> 7) + (0x01010101u - (((~gem) & M7) >> 7));
            if (dx == 0) s3c[blk * 4 + g] = cls;  // byte o: 2=pos,1=zero,0=neg
        }
    }
    __syncthreads();

    // ---- pack ternary s3 into plus/minus bitmasks (fc order o*144+p) ----
    {
        const uint8_t* s3b = (const uint8_t*)s3c;
        int o0 = tid / 144;                 // 0 or 1
        int p  = tid - o0 * 144;
        int base = p * 16 + o0;
        #pragma unroll
        for (int it = 0; it < 8; it++) {
            uint32_t v = s3b[base + 2 * it];
            uint32_t Pm = __ballot_sync(FULLMASK, v == 2u);
            uint32_t Mm = __ballot_sync(FULLMASK, v == 0u);
            if (lane == 0) { Pw[it * 9 + warp] = Pm; Mw[it * 9 + warp] = Mm; }
        }
    }
    __syncthreads();

    // ---- FC via AND+popcount ----
    for (int rep = 0; rep < 2; rep++) {
        if (rep == 1 && warp != 0) break;
        int k = (rep == 0) ? warp : 9;
        int acc = 0, c = 0;
        for (int wd = lane; wd < 72; wd += 32) {
            uint32_t p = Pw[wd], m = Mw[wd], wk = g_fcb[k * 72 + wd];
            acc += __popc(p & wk) - __popc(m & wk);
            c   += __popc(m) - __popc(p);
        }
        #pragma unroll
        for (int off = 16; off; off >>= 1) {
            acc += __shfl_xor_sync(FULLMASK, acc, off);
            c   += __shfl_xor_sync(FULLMASK, c, off);
        }
        if (lane == 0) lg[k] = 2 * acc + c;
    }
    __syncthreads();

    // ---- log_softmax over 10 logits ----
    if (warp == 0) {
        float v = (lane < 10) ? (float)lg[lane] : -3.0e38f;
        float mx = v;
        #pragma unroll
        for (int off = 16; off; off >>= 1) mx = fmaxf(mx, __shfl_xor_sync(FULLMASK, mx, off));
        float e = (lane < 10) ? expf(v - mx) : 0.f;
        float s = e;
        #pragma unroll
        for (int off = 16; off; off >>= 1) s += __shfl_xor_sync(FULLMASK, s, off);
        if (lane < 10) out[b * 10 + lane] = v - mx - logf(s);
    }
}

// ---------------------------------------------------------------------------
extern "C" void kernel_launch(void* const* d_in, const int* in_sizes, int n_in,
                              void* d_out, int out_size) {
    const float* x   = (const float*)d_in[0];   // [8192,1,28,28]
    const float* w1  = (const float*)d_in[1];   // [16,1,3,3]
    const float* w2  = (const float*)d_in[2];   // [16,16,3,3]
    const float* fcw = (const float*)d_in[3];   // [10,2304]
    float* out = (float*)d_out;                 // [8192,10]

    int batch = in_sizes[0] / 784;

    bnn_prep_a<<<474, 256>>>(w1, w2, fcw);
    bnn_prep_b<<<4096, 256>>>();
    bnn_kernel<<<batch, 288>>>(x, out);
}